// round 13
// baseline (speedup 1.0000x reference)
#include <cuda_runtime.h>
#include <cuda_bf16.h>
#include <stdint.h>
#include <math.h>

// ---------------------------------------------------------------------------
// Problem constants
// ---------------------------------------------------------------------------
#define NNODES   50000
#define NEDGES   800000
#define IN_DIM   128
#define HIDDEN   64
#define HEADS    4
#define NGRAPHS  256
#define HC1      256
#define NEG_SLOPE 0.2f

#define GBM 128
#define GBN 64
#define GBK 16
#define WSTR 12

// ---------------------------------------------------------------------------
// Device scratch (pad node-feature buffers by one m-tile so GEMM loads need
// no bounds check; pad region is never written -> stays zero)
// ---------------------------------------------------------------------------
__device__ __nv_bfloat16 g_hw[(size_t)NNODES * HC1];
__device__ __nv_bfloat16 g_xbf[(size_t)(NNODES + GBM) * IN_DIM];
__device__ __nv_bfloat16 g_featb[(size_t)(NNODES + GBM) * HC1];
__device__ __nv_bfloat16 g_W1h[HC1 * IN_DIM], g_W1l[HC1 * IN_DIM];
__device__ __nv_bfloat16 g_W2h[HC1 * HC1],   g_W2l[HC1 * HC1];
__device__ __nv_bfloat16 g_W3h[HIDDEN * HC1], g_W3l[HIDDEN * HC1];
__device__ float g_alo[NNODES * HEADS];
__device__ float g_ahi[NNODES * HEADS];
__device__ int   g_off[NNODES + 1];
__device__ int   g_fill[NNODES];
__device__ int   g_csr[NEDGES];
__device__ float g_pool[NGRAPHS * HIDDEN];
__device__ float g_cnt[NGRAPHS];

// ---------------------------------------------------------------------------
// Pre-conversion kernels
// ---------------------------------------------------------------------------
__global__ void k_xcvt(const float* __restrict__ x) {
    int i = blockIdx.x * blockDim.x + threadIdx.x;
    if (i < NNODES * IN_DIM / 2) {
        float2 v = ((const float2*)x)[i];
        __nv_bfloat162 p(__float2bfloat16(v.x), __float2bfloat16(v.y));
        ((__nv_bfloat162*)g_xbf)[i] = p;
    }
}

// Truncation split of all three weight matrices: hi = trunc16(w), lo = bf16(w-hi)
__global__ void k_splitW(const float* __restrict__ W1, const float* __restrict__ W2,
                         const float* __restrict__ W3) {
    const int S1 = HC1 * IN_DIM, S2 = HC1 * HC1, S3 = HIDDEN * HC1;
    int i = blockIdx.x * blockDim.x + threadIdx.x;
    const float* src; __nv_bfloat16 *dh, *dl; int idx;
    if (i < S1)           { src = W1; dh = g_W1h; dl = g_W1l; idx = i; }
    else if (i < S1 + S2) { src = W2; dh = g_W2h; dl = g_W2l; idx = i - S1; }
    else if (i < S1 + S2 + S3) { src = W3; dh = g_W3h; dl = g_W3l; idx = i - S1 - S2; }
    else return;
    float w = src[idx];
    unsigned int b = __float_as_uint(w);
    unsigned short hb = (unsigned short)(b >> 16);
    float hi = __uint_as_float(b & 0xffff0000u);
    __nv_bfloat16 h; *(unsigned short*)&h = hb;
    dh[idx] = h;
    dl[idx] = __float2bfloat16(w - hi);
}

// ---------------------------------------------------------------------------
// CSR build
// ---------------------------------------------------------------------------
__global__ void k_zero_csr() {
    int i = blockIdx.x * blockDim.x + threadIdx.x;
    if (i <= NNODES) g_off[i] = 0;
    if (i < NGRAPHS * HIDDEN) g_pool[i] = 0.f;
    if (i < NGRAPHS) g_cnt[i] = 0.f;
}

__global__ void k_hist(const int* __restrict__ dst) {
    int e = blockIdx.x * blockDim.x + threadIdx.x;
    if (e < NEDGES) atomicAdd(&g_off[dst[e] + 1], 1);
}

__global__ void k_scan() {
    __shared__ int wsum[32];
    __shared__ int carry;
    int t = threadIdx.x, lane = t & 31, wid = t >> 5;
    if (t == 0) carry = 0;
    __syncthreads();
    for (int base = 0; base < NNODES; base += 1024) {
        int i = base + t;
        int cnt = (i < NNODES) ? g_off[i + 1] : 0;
        int v = cnt;
        #pragma unroll
        for (int off = 1; off < 32; off <<= 1) {
            int nb = __shfl_up_sync(0xffffffffu, v, off);
            if (lane >= off) v += nb;
        }
        if (lane == 31) wsum[wid] = v;
        __syncthreads();
        if (wid == 0) {
            int s = wsum[lane];
            #pragma unroll
            for (int off = 1; off < 32; off <<= 1) {
                int nb = __shfl_up_sync(0xffffffffu, s, off);
                if (lane >= off) s += nb;
            }
            wsum[lane] = s;
        }
        __syncthreads();
        int add = carry + (wid > 0 ? wsum[wid - 1] : 0);
        int inc = v + add;
        if (i < NNODES) { g_off[i + 1] = inc; g_fill[i] = inc - cnt; }
        __syncthreads();
        if (t == 0) carry += wsum[31];
        __syncthreads();
    }
}

__global__ void k_scatter(const int* __restrict__ src, const int* __restrict__ dst) {
    int e = blockIdx.x * blockDim.x + threadIdx.x;
    if (e < NEDGES) {
        int p = atomicAdd(&g_fill[dst[e]], 1);
        g_csr[p] = src[e];
    }
}

// ---------------------------------------------------------------------------
// GEMM helpers
// ---------------------------------------------------------------------------
__device__ __forceinline__ void mma_bf16(float* d, const unsigned int* a, const unsigned int* b) {
    asm volatile(
        "mma.sync.aligned.m16n8k16.row.col.f32.bf16.bf16.f32 "
        "{%0,%1,%2,%3}, {%4,%5,%6,%7}, {%8,%9}, {%0,%1,%2,%3};\n"
        : "+f"(d[0]), "+f"(d[1]), "+f"(d[2]), "+f"(d[3])
        : "r"(a[0]), "r"(a[1]), "r"(a[2]), "r"(a[3]), "r"(b[0]), "r"(b[1]));
}

__device__ __forceinline__ void ldsm_x4(unsigned int* r, unsigned int addr) {
    asm volatile("ldmatrix.sync.aligned.m8n8.x4.shared.b16 {%0,%1,%2,%3}, [%4];"
        : "=r"(r[0]), "=r"(r[1]), "=r"(r[2]), "=r"(r[3]) : "r"(addr));
}

__device__ __forceinline__ unsigned int cvt_bf16x2(float hi, float lo) {
    unsigned int r; asm("cvt.rn.bf16x2.f32 %0, %1, %2;" : "=r"(r) : "f"(hi), "f"(lo)); return r;
}

// ---------------------------------------------------------------------------
// GEMM: all-bf16 inputs. 128x64 tile, 256 threads, 8 warps (4m x 2n),
// warp tile 32x32. A plain bf16; B pre-split (hi/lo) in gmem.
// k-loop has ZERO conversion math: LDG.128 -> STS.128 -> LDSM -> MMA.
// Fused attention-coefficient epilogue.
// ---------------------------------------------------------------------------
__global__ __launch_bounds__(256) void k_gemm_bb(
    const __nv_bfloat16* __restrict__ A,
    const __nv_bfloat16* __restrict__ Bh, const __nv_bfloat16* __restrict__ Bl,
    __nv_bfloat16* __restrict__ C, int M, int Nn, int K,
    const float* __restrict__ a_src, const float* __restrict__ a_dst,
    float* __restrict__ alo, float* __restrict__ ahi, int H) {
    __shared__ __align__(16) unsigned int sA[GBM * WSTR];
    __shared__ __align__(16) unsigned int sBh[GBN * WSTR], sBl[GBN * WSTR];
    __shared__ float s_alo[GBM], s_ahi[GBM];

    int t = threadIdx.x;
    int lane = t & 31, warp = t >> 5;
    int wm = warp >> 1, wn = warp & 1;
    int m0 = blockIdx.y * GBM, n0 = blockIdx.x * GBN;
    int head = blockIdx.x;

    if (t < GBM) { s_alo[t] = 0.f; s_ahi[t] = 0.f; }

    // A fill: thread t covers row=t>>1, 16B half=(t&1). Padded buffer: no guard.
    int arow = t >> 1, ahalf = t & 1;
    const __nv_bfloat16* pA = A + (size_t)(m0 + arow) * K + ahalf * 8;
    int wA = arow * WSTR + ahalf * 4;
    // B fill: t<128 -> hi array, t>=128 -> lo array; within: row=(u>>1), half=(u&1)
    int u = t & 127;
    int brow = u >> 1, bhalf = u & 1;
    const __nv_bfloat16* pB = ((t < 128) ? Bh : Bl) + (size_t)(n0 + brow) * K + bhalf * 8;
    unsigned int* sB = (t < 128) ? sBh : sBl;
    int wB = brow * WSTR + bhalf * 4;

    unsigned int aBase = (unsigned int)__cvta_generic_to_shared(sA);
    unsigned int bHi = (unsigned int)__cvta_generic_to_shared(sBh);
    unsigned int bLo = (unsigned int)__cvta_generic_to_shared(sBl);
    unsigned int aAddr[2], bAddr[2], blAddr[2];
    #pragma unroll
    for (int mi = 0; mi < 2; mi++) {
        int r = wm * 32 + mi * 16 + (lane & 15);
        aAddr[mi] = aBase + (unsigned int)(r * WSTR * 4) + (((lane >> 4) & 1) * 16);
    }
    #pragma unroll
    for (int p = 0; p < 2; p++) {
        int r = wn * 32 + p * 16 + (((lane >> 4) & 1) * 8) + (lane & 7);
        unsigned int off = (unsigned int)(r * WSTR * 4) + (((lane >> 3) & 1) * 16);
        bAddr[p] = bHi + off; blAddr[p] = bLo + off;
    }

    float acc[2][4][4];
    #pragma unroll
    for (int i = 0; i < 2; i++)
        #pragma unroll
        for (int j = 0; j < 4; j++)
            #pragma unroll
            for (int k = 0; k < 4; k++) acc[i][j][k] = 0.f;

    for (int k0 = 0; k0 < K; k0 += GBK) {
        uint4 va = *(const uint4*)(pA + k0);
        uint4 vb = *(const uint4*)(pB + k0);
        *(uint4*)&sA[wA] = va;
        *(uint4*)&sB[wB] = vb;
        __syncthreads();

        unsigned int ah[2][4];
        ldsm_x4(ah[0], aAddr[0]);
        ldsm_x4(ah[1], aAddr[1]);
        unsigned int bq[4], blq[4];
        unsigned int bh[4][2], bl[4][2];
        ldsm_x4(bq, bAddr[0]);
        bh[0][0] = bq[0]; bh[0][1] = bq[1]; bh[1][0] = bq[2]; bh[1][1] = bq[3];
        ldsm_x4(bq, bAddr[1]);
        bh[2][0] = bq[0]; bh[2][1] = bq[1]; bh[3][0] = bq[2]; bh[3][1] = bq[3];
        ldsm_x4(blq, blAddr[0]);
        bl[0][0] = blq[0]; bl[0][1] = blq[1]; bl[1][0] = blq[2]; bl[1][1] = blq[3];
        ldsm_x4(blq, blAddr[1]);
        bl[2][0] = blq[0]; bl[2][1] = blq[1]; bl[3][0] = blq[2]; bl[3][1] = blq[3];

        #pragma unroll
        for (int mi = 0; mi < 2; mi++)
            #pragma unroll
            for (int ni = 0; ni < 4; ni++) {
                mma_bf16(acc[mi][ni], ah[mi], bh[ni]);
                mma_bf16(acc[mi][ni], ah[mi], bl[ni]);
            }
        __syncthreads();
    }

    // ---- epilogue: bf16 C store + fused alo/ahi ----
    const float* as_h = a_src + head * 64;
    const float* ad_h = a_dst + head * 64;
    float sl[4] = {0.f,0.f,0.f,0.f};
    float sh_[4] = {0.f,0.f,0.f,0.f};
    #pragma unroll
    for (int mi = 0; mi < 2; mi++) {
        int r0 = m0 + wm * 32 + mi * 16 + (lane >> 2);
        #pragma unroll
        for (int ni = 0; ni < 4; ni++) {
            int cl = wn * 32 + ni * 8 + (lane & 3) * 2;
            float as0 = as_h[cl], as1 = as_h[cl + 1];
            float ad0 = ad_h[cl], ad1 = ad_h[cl + 1];
            sl[mi * 2 + 0] += acc[mi][ni][0] * as0 + acc[mi][ni][1] * as1;
            sh_[mi * 2 + 0] += acc[mi][ni][0] * ad0 + acc[mi][ni][1] * ad1;
            sl[mi * 2 + 1] += acc[mi][ni][2] * as0 + acc[mi][ni][3] * as1;
            sh_[mi * 2 + 1] += acc[mi][ni][2] * ad0 + acc[mi][ni][3] * ad1;
            int c = n0 + cl;
            if (r0 < M) {
                __nv_bfloat162 p(__float2bfloat16(acc[mi][ni][0]), __float2bfloat16(acc[mi][ni][1]));
                *(__nv_bfloat162*)&C[(size_t)r0 * Nn + c] = p;
            }
            if (r0 + 8 < M) {
                __nv_bfloat162 p(__float2bfloat16(acc[mi][ni][2]), __float2bfloat16(acc[mi][ni][3]));
                *(__nv_bfloat162*)&C[(size_t)(r0 + 8) * Nn + c] = p;
            }
        }
    }
    #pragma unroll
    for (int off = 1; off <= 2; off <<= 1)
        #pragma unroll
        for (int i = 0; i < 4; i++) {
            sl[i] += __shfl_xor_sync(0xffffffffu, sl[i], off);
            sh_[i] += __shfl_xor_sync(0xffffffffu, sh_[i], off);
        }
    if ((lane & 3) == 0) {
        #pragma unroll
        for (int mi = 0; mi < 2; mi++) {
            int rl = wm * 32 + mi * 16 + (lane >> 2);
            atomicAdd(&s_alo[rl], sl[mi * 2]);
            atomicAdd(&s_ahi[rl], sh_[mi * 2]);
            atomicAdd(&s_alo[rl + 8], sl[mi * 2 + 1]);
            atomicAdd(&s_ahi[rl + 8], sh_[mi * 2 + 1]);
        }
    }
    __syncthreads();
    if (t < GBM && m0 + t < M) {
        alo[(m0 + t) * H + head] = s_alo[t];
        ahi[(m0 + t) * H + head] = s_ahi[t];
    }
}

// ---------------------------------------------------------------------------
// Packed f32x2 helpers
// ---------------------------------------------------------------------------
__device__ __forceinline__ unsigned long long pk2(unsigned int lo, unsigned int hi) {
    unsigned long long r;
    asm("mov.b64 %0, {%1,%2};" : "=l"(r) : "r"(lo), "r"(hi));
    return r;
}
__device__ __forceinline__ void ffma2(unsigned long long& acc, unsigned long long a, unsigned long long b) {
    asm("fma.rn.f32x2 %0, %1, %2, %0;" : "+l"(acc) : "l"(a), "l"(b));
}
__device__ __forceinline__ float2 upk2(unsigned long long v) {
    unsigned int lo, hi;
    asm("mov.b64 {%0,%1}, %2;" : "=r"(lo), "=r"(hi) : "l"(v));
    return make_float2(__uint_as_float(lo), __uint_as_float(hi));
}
__device__ __forceinline__ unsigned long long bf2f32x2(unsigned int r) {
    return pk2(r << 16, r & 0xffff0000u);
}

__device__ __forceinline__ float lrelu(float x) { return x > 0.f ? x : NEG_SLOPE * x; }

// ---------------------------------------------------------------------------
// Aggregation (layers 1/2, H=4): single-pass unnormalized softmax.
// Output written as bf16 (identical rounding point to the GEMM's former
// A-side conversion -> bit-identical math, half the traffic).
// ---------------------------------------------------------------------------
__global__ void k_aggregate4(const __nv_bfloat16* __restrict__ hw,
                             const float* __restrict__ alo,
                             const float* __restrict__ ahi,
                             const float* __restrict__ bias,
                             __nv_bfloat16* __restrict__ out) {
    const int H = 4, HCn = 256, FPL = 8;
    int warp = (blockIdx.x * blockDim.x + threadIdx.x) >> 5;
    int lane = threadIdx.x & 31;
    if (warp >= NNODES) return;
    int n = warp;
    int beg = g_off[n], deg = g_off[n + 1] - beg;

    int hh_l = lane >> 3;
    float my_a = ahi[n * H + hh_l];

    unsigned long long acc2[4] = {0ull, 0ull, 0ull, 0ull};
    float den = 0.f;

    const int total = deg + 1;
    int j = 0;
    for (; j + 1 < total; j += 2) {
        int s0 = g_csr[beg + j];
        int s1 = (j + 1 < deg) ? g_csr[beg + j + 1] : n;
        uint4 r0 = *(const uint4*)(hw + (size_t)s0 * HCn + lane * FPL);
        uint4 r1 = *(const uint4*)(hw + (size_t)s1 * HCn + lane * FPL);
        float w0 = __expf(lrelu(alo[s0 * H + hh_l] + my_a));
        float w1 = __expf(lrelu(alo[s1 * H + hh_l] + my_a));
        den += w0 + w1;
        unsigned long long w20 = pk2(__float_as_uint(w0), __float_as_uint(w0));
        unsigned long long w21 = pk2(__float_as_uint(w1), __float_as_uint(w1));
        ffma2(acc2[0], bf2f32x2(r0.x), w20);
        ffma2(acc2[1], bf2f32x2(r0.y), w20);
        ffma2(acc2[2], bf2f32x2(r0.z), w20);
        ffma2(acc2[3], bf2f32x2(r0.w), w20);
        ffma2(acc2[0], bf2f32x2(r1.x), w21);
        ffma2(acc2[1], bf2f32x2(r1.y), w21);
        ffma2(acc2[2], bf2f32x2(r1.z), w21);
        ffma2(acc2[3], bf2f32x2(r1.w), w21);
    }
    if (j < total) {
        int s = (j < deg) ? g_csr[beg + j] : n;
        uint4 r = *(const uint4*)(hw + (size_t)s * HCn + lane * FPL);
        float w = __expf(lrelu(alo[s * H + hh_l] + my_a));
        den += w;
        unsigned long long w2 = pk2(__float_as_uint(w), __float_as_uint(w));
        ffma2(acc2[0], bf2f32x2(r.x), w2);
        ffma2(acc2[1], bf2f32x2(r.y), w2);
        ffma2(acc2[2], bf2f32x2(r.z), w2);
        ffma2(acc2[3], bf2f32x2(r.w), w2);
    }
    float inv_d = 1.f / (den + 1e-16f);
    unsigned int wds[4];
    #pragma unroll
    for (int k = 0; k < 4; k++) {
        float2 a = upk2(acc2[k]);
        float v0 = a.x * inv_d + bias[lane * FPL + 2 * k];
        float v1 = a.y * inv_d + bias[lane * FPL + 2 * k + 1];
        v0 = (v0 > 0.f) ? v0 : expm1f(v0);
        v1 = (v1 > 0.f) ? v1 : expm1f(v1);
        wds[k] = cvt_bf16x2(v1, v0);
    }
    *(uint4*)(out + (size_t)n * HCn + lane * FPL) = make_uint4(wds[0], wds[1], wds[2], wds[3]);
}

// ---------------------------------------------------------------------------
// Layer-3 aggregation (H=1), single pass, fused with mean-pool accumulation.
// ---------------------------------------------------------------------------
__global__ void k_aggregate1_pool(const __nv_bfloat16* __restrict__ hw,
                                  const float* __restrict__ alo,
                                  const float* __restrict__ ahi,
                                  const float* __restrict__ bias,
                                  const int* __restrict__ batch) {
    const int HCn = 64, FPL = 2;
    int warp = (blockIdx.x * blockDim.x + threadIdx.x) >> 5;
    int lane = threadIdx.x & 31;
    if (warp >= NNODES) return;
    int n = warp;
    int beg = g_off[n], deg = g_off[n + 1] - beg;

    float ahin = ahi[n];
    float a0 = 0.f, a1 = 0.f, den = 0.f;
    const int total = deg + 1;
    int j = 0;
    for (; j + 1 < total; j += 2) {
        int s0 = g_csr[beg + j];
        int s1 = (j + 1 < deg) ? g_csr[beg + j + 1] : n;
        unsigned int r0 = *(const unsigned int*)(hw + (size_t)s0 * HCn + lane * FPL);
        unsigned int r1 = *(const unsigned int*)(hw + (size_t)s1 * HCn + lane * FPL);
        float w0 = __expf(lrelu(alo[s0] + ahin));
        float w1 = __expf(lrelu(alo[s1] + ahin));
        den += w0 + w1;
        float2 f0 = __bfloat1622float2(*(__nv_bfloat162*)&r0);
        float2 f1 = __bfloat1622float2(*(__nv_bfloat162*)&r1);
        a0 += w0 * f0.x + w1 * f1.x;
        a1 += w0 * f0.y + w1 * f1.y;
    }
    if (j < total) {
        int s = (j < deg) ? g_csr[beg + j] : n;
        unsigned int r = *(const unsigned int*)(hw + (size_t)s * HCn + lane * FPL);
        float w = __expf(lrelu(alo[s] + ahin));
        den += w;
        float2 f = __bfloat1622float2(*(__nv_bfloat162*)&r);
        a0 += w * f.x; a1 += w * f.y;
    }
    float inv_d = 1.f / (den + 1e-16f);
    float v0 = a0 * inv_d + bias[lane * FPL];
    float v1 = a1 * inv_d + bias[lane * FPL + 1];
    v0 = (v0 > 0.f) ? v0 : expm1f(v0);
    v1 = (v1 > 0.f) ? v1 : expm1f(v1);

    int b = batch[n];
    atomicAdd(&g_pool[b * HIDDEN + lane * FPL], v0);
    atomicAdd(&g_pool[b * HIDDEN + lane * FPL + 1], v1);
    if (lane == 0) atomicAdd(&g_cnt[b], 1.f);
}

// ---------------------------------------------------------------------------
// Heads MLP
// ---------------------------------------------------------------------------
__global__ void k_mlp(const float* __restrict__ Wc1, const float* __restrict__ bc1,
                      const float* __restrict__ Wc2, const float* __restrict__ bc2,
                      const float* __restrict__ Wr1, const float* __restrict__ br1,
                      const float* __restrict__ Wr2, const float* __restrict__ br2,
                      float* __restrict__ out) {
    int warp = (blockIdx.x * blockDim.x + threadIdx.x) >> 5;
    int lane = threadIdx.x & 31;
    if (warp >= NGRAPHS) return;
    float inv_cnt = 1.f / fmaxf(g_cnt[warp], 1.f);
    const float* gp = &g_pool[warp * HIDDEN];

    {
        float h0 = bc1[lane], h1 = bc1[lane + 32];
        for (int c = 0; c < HIDDEN; c++) {
            float gc = gp[c] * inv_cnt;
            h0 += Wc1[lane * HIDDEN + c] * gc;
            h1 += Wc1[(lane + 32) * HIDDEN + c] * gc;
        }
        h0 = fmaxf(h0, 0.f); h1 = fmaxf(h1, 0.f);
        float s = Wc2[lane] * h0 + Wc2[lane + 32] * h1;
        #pragma unroll
        for (int off = 16; off > 0; off >>= 1) s += __shfl_xor_sync(0xffffffffu, s, off);
        if (lane == 0) out[warp] = s + bc2[0];
    }
    {
        float h0 = br1[lane], h1 = br1[lane + 32];
        for (int c = 0; c < HIDDEN; c++) {
            float gc = gp[c] * inv_cnt;
            h0 += Wr1[lane * HIDDEN + c] * gc;
            h1 += Wr1[(lane + 32) * HIDDEN + c] * gc;
        }
        h0 = fmaxf(h0, 0.f); h1 = fmaxf(h1, 0.f);
        float s = Wr2[lane] * h0 + Wr2[lane + 32] * h1;
        #pragma unroll
        for (int off = 16; off > 0; off >>= 1) s += __shfl_xor_sync(0xffffffffu, s, off);
        if (lane == 0) out[NGRAPHS + warp] = s + br2[0];
    }
}

// ---------------------------------------------------------------------------
// Launch
// ---------------------------------------------------------------------------
extern "C" void kernel_launch(void* const* d_in, const int* in_sizes, int n_in,
                              void* d_out, int out_size) {
    const float* x     = (const float*)d_in[0];
    const int*   ei    = (const int*)d_in[1];
    const int*   batch = (const int*)d_in[2];
    const float* W1  = (const float*)d_in[3];
    const float* as1 = (const float*)d_in[4];
    const float* ad1 = (const float*)d_in[5];
    const float* b1  = (const float*)d_in[6];
    const float* W2  = (const float*)d_in[7];
    const float* as2 = (const float*)d_in[8];
    const float* ad2 = (const float*)d_in[9];
    const float* b2  = (const float*)d_in[10];
    const float* W3  = (const float*)d_in[11];
    const float* as3 = (const float*)d_in[12];
    const float* ad3 = (const float*)d_in[13];
    const float* b3  = (const float*)d_in[14];
    const float* Wc1 = (const float*)d_in[15];
    const float* bc1 = (const float*)d_in[16];
    const float* Wc2 = (const float*)d_in[17];
    const float* bc2 = (const float*)d_in[18];
    const float* Wr1 = (const float*)d_in[19];
    const float* br1 = (const float*)d_in[20];
    const float* Wr2 = (const float*)d_in[21];
    const float* br2 = (const float*)d_in[22];
    float* out = (float*)d_out;

    const int* srcp = ei;
    const int* dstp = ei + NEDGES;

    __nv_bfloat16 *hw_p, *xbf_p, *featb_p, *w1h_p, *w1l_p, *w2h_p, *w2l_p, *w3h_p, *w3l_p;
    cudaGetSymbolAddress((void**)&hw_p,    g_hw);
    cudaGetSymbolAddress((void**)&xbf_p,   g_xbf);
    cudaGetSymbolAddress((void**)&featb_p, g_featb);
    cudaGetSymbolAddress((void**)&w1h_p,   g_W1h);
    cudaGetSymbolAddress((void**)&w1l_p,   g_W1l);
    cudaGetSymbolAddress((void**)&w2h_p,   g_W2h);
    cudaGetSymbolAddress((void**)&w2l_p,   g_W2l);
    cudaGetSymbolAddress((void**)&w3h_p,   g_W3h);
    cudaGetSymbolAddress((void**)&w3l_p,   g_W3l);
    float *alo_p, *ahi_p;
    cudaGetSymbolAddress((void**)&alo_p, g_alo);
    cudaGetSymbolAddress((void**)&ahi_p, g_ahi);

    const int warps_grid = (NNODES * 32 + 255) / 256;
    const int mblocks = (NNODES + GBM - 1) / GBM;
    const int wtot = HC1 * IN_DIM + HC1 * HC1 + HIDDEN * HC1;

    k_zero_csr<<<(NNODES + 256) / 256, 256>>>();
    k_xcvt<<<(NNODES * IN_DIM / 2 + 255) / 256, 256>>>(x);
    k_splitW<<<(wtot + 255) / 256, 256>>>(W1, W2, W3);
    k_gemm_bb<<<dim3(HC1 / GBN, mblocks), 256>>>(xbf_p, w1h_p, w1l_p, hw_p, NNODES, HC1, IN_DIM,
                                                 as1, ad1, alo_p, ahi_p, HEADS);
    k_hist<<<(NEDGES + 255) / 256, 256>>>(dstp);
    k_scan<<<1, 1024>>>();
    k_scatter<<<(NEDGES + 255) / 256, 256>>>(srcp, dstp);

    k_aggregate4<<<warps_grid, 256>>>(hw_p, alo_p, ahi_p, b1, featb_p);
    k_gemm_bb<<<dim3(HC1 / GBN, mblocks), 256>>>(featb_p, w2h_p, w2l_p, hw_p, NNODES, HC1, HC1,
                                                 as2, ad2, alo_p, ahi_p, HEADS);
    k_aggregate4<<<warps_grid, 256>>>(hw_p, alo_p, ahi_p, b2, featb_p);
    k_gemm_bb<<<dim3(1, mblocks), 256>>>(featb_p, w3h_p, w3l_p, hw_p, NNODES, HIDDEN, HC1,
                                         as3, ad3, alo_p, ahi_p, 1);
    k_aggregate1_pool<<<warps_grid, 256>>>(hw_p, alo_p, ahi_p, b3, batch);

    k_mlp<<<(NGRAPHS * 32 + 255) / 256, 256>>>(Wc1, bc1, Wc2, bc2, Wr1, br1, Wr2, br2, out);
}

// round 15
// speedup vs baseline: 1.0263x; 1.0263x over previous
#include <cuda_runtime.h>
#include <cuda_bf16.h>
#include <stdint.h>
#include <math.h>

// ---------------------------------------------------------------------------
// Problem constants
// ---------------------------------------------------------------------------
#define NNODES   50000
#define NEDGES   800000
#define IN_DIM   128
#define HIDDEN   64
#define HEADS    4
#define NGRAPHS  256
#define HC1      256
#define NEG_SLOPE 0.2f

#define GBM 128
#define GBK 16
#define WSTR 12

// ---------------------------------------------------------------------------
// Device scratch (node-feature buffers padded by one m-tile)
// ---------------------------------------------------------------------------
__device__ __nv_bfloat16 g_hw[(size_t)NNODES * HC1];
__device__ __nv_bfloat16 g_xbf[(size_t)(NNODES + GBM) * IN_DIM];
__device__ __nv_bfloat16 g_featb[(size_t)(NNODES + GBM) * HC1];
__device__ __nv_bfloat16 g_W1h[HC1 * IN_DIM], g_W1l[HC1 * IN_DIM];
__device__ __nv_bfloat16 g_W2h[HC1 * HC1],   g_W2l[HC1 * HC1];
__device__ __nv_bfloat16 g_W3h[HIDDEN * HC1], g_W3l[HIDDEN * HC1];
__device__ float g_alo[NNODES * HEADS];
__device__ float g_ahi[NNODES * HEADS];
__device__ int   g_off[NNODES + 1];
__device__ int   g_fill[NNODES];
__device__ int   g_csr[NEDGES];
__device__ float g_pool[NGRAPHS * HIDDEN];
__device__ float g_cnt[NGRAPHS];

// ---------------------------------------------------------------------------
// Zero kernel (must precede hist)
// ---------------------------------------------------------------------------
__global__ void k_zero_csr() {
    int i = blockIdx.x * blockDim.x + threadIdx.x;
    if (i <= NNODES) g_off[i] = 0;
    if (i < NGRAPHS * HIDDEN) g_pool[i] = 0.f;
    if (i < NGRAPHS) g_cnt[i] = 0.f;
}

// ---------------------------------------------------------------------------
// Fused pre-pass: x->bf16, weight split, dst histogram (independent jobs)
// ---------------------------------------------------------------------------
__global__ void k_pre(const float* __restrict__ x,
                      const float* __restrict__ W1, const float* __restrict__ W2,
                      const float* __restrict__ W3, const int* __restrict__ dst) {
    int i = blockIdx.x * blockDim.x + threadIdx.x;
    if (i < NNODES * IN_DIM / 2) {
        float2 v = ((const float2*)x)[i];
        __nv_bfloat162 p(__float2bfloat16(v.x), __float2bfloat16(v.y));
        ((__nv_bfloat162*)g_xbf)[i] = p;
    }
    if (i < NEDGES) atomicAdd(&g_off[dst[i] + 1], 1);
    const int S1 = HC1 * IN_DIM, S2 = HC1 * HC1, S3 = HIDDEN * HC1;
    if (i < S1 + S2 + S3) {
        const float* src; __nv_bfloat16 *dh, *dl; int idx;
        if (i < S1)           { src = W1; dh = g_W1h; dl = g_W1l; idx = i; }
        else if (i < S1 + S2) { src = W2; dh = g_W2h; dl = g_W2l; idx = i - S1; }
        else                  { src = W3; dh = g_W3h; dl = g_W3l; idx = i - S1 - S2; }
        float w = src[idx];
        unsigned int b = __float_as_uint(w);
        float hi = __uint_as_float(b & 0xffff0000u);
        __nv_bfloat16 h; *(unsigned short*)&h = (unsigned short)(b >> 16);
        dh[idx] = h;
        dl[idx] = __float2bfloat16(w - hi);
    }
}

__global__ void k_scan() {
    __shared__ int wsum[32];
    __shared__ int carry;
    int t = threadIdx.x, lane = t & 31, wid = t >> 5;
    if (t == 0) carry = 0;
    __syncthreads();
    for (int base = 0; base < NNODES; base += 1024) {
        int i = base + t;
        int cnt = (i < NNODES) ? g_off[i + 1] : 0;
        int v = cnt;
        #pragma unroll
        for (int off = 1; off < 32; off <<= 1) {
            int nb = __shfl_up_sync(0xffffffffu, v, off);
            if (lane >= off) v += nb;
        }
        if (lane == 31) wsum[wid] = v;
        __syncthreads();
        if (wid == 0) {
            int s = wsum[lane];
            #pragma unroll
            for (int off = 1; off < 32; off <<= 1) {
                int nb = __shfl_up_sync(0xffffffffu, s, off);
                if (lane >= off) s += nb;
            }
            wsum[lane] = s;
        }
        __syncthreads();
        int add = carry + (wid > 0 ? wsum[wid - 1] : 0);
        int inc = v + add;
        if (i < NNODES) { g_off[i + 1] = inc; g_fill[i] = inc - cnt; }
        __syncthreads();
        if (t == 0) carry += wsum[31];
        __syncthreads();
    }
}

__global__ void k_scatter(const int* __restrict__ src, const int* __restrict__ dst) {
    int e = blockIdx.x * blockDim.x + threadIdx.x;
    if (e < NEDGES) {
        int p = atomicAdd(&g_fill[dst[e]], 1);
        g_csr[p] = src[e];
    }
}

// ---------------------------------------------------------------------------
// GEMM helpers
// ---------------------------------------------------------------------------
__device__ __forceinline__ void mma_bf16(float* d, const unsigned int* a, const unsigned int* b) {
    asm volatile(
        "mma.sync.aligned.m16n8k16.row.col.f32.bf16.bf16.f32 "
        "{%0,%1,%2,%3}, {%4,%5,%6,%7}, {%8,%9}, {%0,%1,%2,%3};\n"
        : "+f"(d[0]), "+f"(d[1]), "+f"(d[2]), "+f"(d[3])
        : "r"(a[0]), "r"(a[1]), "r"(a[2]), "r"(a[3]), "r"(b[0]), "r"(b[1]));
}

__device__ __forceinline__ void ldsm_x4(unsigned int* r, unsigned int addr) {
    asm volatile("ldmatrix.sync.aligned.m8n8.x4.shared.b16 {%0,%1,%2,%3}, [%4];"
        : "=r"(r[0]), "=r"(r[1]), "=r"(r[2]), "=r"(r[3]) : "r"(addr));
}

__device__ __forceinline__ unsigned int cvt_bf16x2(float hi, float lo) {
    unsigned int r; asm("cvt.rn.bf16x2.f32 %0, %1, %2;" : "=r"(r) : "f"(hi), "f"(lo)); return r;
}

// ---------------------------------------------------------------------------
// Wide GEMM (layers 1-2): 128x128 tile, 256 threads, 8 warps (2m x 4n),
// warp tile 64x32 -> LDSM/MMA ratio 0.25 (vs 0.375). A plain bf16, B split.
// Two heads per CTA; fused attention-coefficient epilogue.
// ---------------------------------------------------------------------------
__global__ __launch_bounds__(256) void k_gemm_w(
    const __nv_bfloat16* __restrict__ A,
    const __nv_bfloat16* __restrict__ Bh, const __nv_bfloat16* __restrict__ Bl,
    __nv_bfloat16* __restrict__ C, int M, int Nn, int K,
    const float* __restrict__ a_src, const float* __restrict__ a_dst,
    float* __restrict__ alo, float* __restrict__ ahi, int H) {
    __shared__ __align__(16) unsigned int sA[GBM * WSTR];
    __shared__ __align__(16) unsigned int sBh[128 * WSTR], sBl[128 * WSTR];
    __shared__ float s_alo[GBM * 2], s_ahi[GBM * 2];

    int t = threadIdx.x;
    int lane = t & 31, warp = t >> 5;
    int wm = warp >> 2, wn = warp & 3;          // 2m x 4n
    int m0 = blockIdx.y * GBM, n0 = blockIdx.x * 128;
    int headbase = blockIdx.x * 2;
    int head_local = wn >> 1;                   // wn 0,1 -> head0; 2,3 -> head1

    if (t < GBM * 2) { s_alo[t] = 0.f; s_ahi[t] = 0.f; }

    // fills: 1 uint4 each for A, Bh, Bl per thread per ktile
    int row = t >> 1, half = t & 1;
    const __nv_bfloat16* pA  = A  + (size_t)(m0 + row) * K + half * 8;
    const __nv_bfloat16* pBh = Bh + (size_t)(n0 + row) * K + half * 8;
    const __nv_bfloat16* pBl = Bl + (size_t)(n0 + row) * K + half * 8;
    int wI = row * WSTR + half * 4;

    unsigned int aBase = (unsigned int)__cvta_generic_to_shared(sA);
    unsigned int bHi = (unsigned int)__cvta_generic_to_shared(sBh);
    unsigned int bLo = (unsigned int)__cvta_generic_to_shared(sBl);
    unsigned int aAddr[4], bAddr[2], blAddr[2];
    #pragma unroll
    for (int mi = 0; mi < 4; mi++) {
        int r = wm * 64 + mi * 16 + (lane & 15);
        aAddr[mi] = aBase + (unsigned int)(r * WSTR * 4) + (((lane >> 4) & 1) * 16);
    }
    #pragma unroll
    for (int p = 0; p < 2; p++) {
        int r = wn * 32 + p * 16 + (((lane >> 4) & 1) * 8) + (lane & 7);
        unsigned int off = (unsigned int)(r * WSTR * 4) + (((lane >> 3) & 1) * 16);
        bAddr[p] = bHi + off; blAddr[p] = bLo + off;
    }

    float acc[4][4][4];
    #pragma unroll
    for (int i = 0; i < 4; i++)
        #pragma unroll
        for (int j = 0; j < 4; j++)
            #pragma unroll
            for (int k = 0; k < 4; k++) acc[i][j][k] = 0.f;

    for (int k0 = 0; k0 < K; k0 += GBK) {
        *(uint4*)&sA[wI]  = *(const uint4*)(pA + k0);
        *(uint4*)&sBh[wI] = *(const uint4*)(pBh + k0);
        *(uint4*)&sBl[wI] = *(const uint4*)(pBl + k0);
        __syncthreads();

        unsigned int ah[4][4];
        ldsm_x4(ah[0], aAddr[0]);
        ldsm_x4(ah[1], aAddr[1]);
        ldsm_x4(ah[2], aAddr[2]);
        ldsm_x4(ah[3], aAddr[3]);
        unsigned int bq[4], blq[4];
        unsigned int bh[4][2], bl[4][2];
        ldsm_x4(bq, bAddr[0]);
        bh[0][0] = bq[0]; bh[0][1] = bq[1]; bh[1][0] = bq[2]; bh[1][1] = bq[3];
        ldsm_x4(bq, bAddr[1]);
        bh[2][0] = bq[0]; bh[2][1] = bq[1]; bh[3][0] = bq[2]; bh[3][1] = bq[3];
        ldsm_x4(blq, blAddr[0]);
        bl[0][0] = blq[0]; bl[0][1] = blq[1]; bl[1][0] = blq[2]; bl[1][1] = blq[3];
        ldsm_x4(blq, blAddr[1]);
        bl[2][0] = blq[0]; bl[2][1] = blq[1]; bl[3][0] = blq[2]; bl[3][1] = blq[3];

        #pragma unroll
        for (int mi = 0; mi < 4; mi++)
            #pragma unroll
            for (int ni = 0; ni < 4; ni++) {
                mma_bf16(acc[mi][ni], ah[mi], bh[ni]);
                mma_bf16(acc[mi][ni], ah[mi], bl[ni]);
            }
        __syncthreads();
    }

    // ---- epilogue: bf16 C store + fused alo/ahi (per-head) ----
    const float* as_h = a_src + (headbase + head_local) * 64;
    const float* ad_h = a_dst + (headbase + head_local) * 64;
    float sl[8], sh_[8];
    #pragma unroll
    for (int i = 0; i < 8; i++) { sl[i] = 0.f; sh_[i] = 0.f; }
    #pragma unroll
    for (int mi = 0; mi < 4; mi++) {
        int r0 = m0 + wm * 64 + mi * 16 + (lane >> 2);
        #pragma unroll
        for (int ni = 0; ni < 4; ni++) {
            int cl_h = (wn & 1) * 32 + ni * 8 + (lane & 3) * 2;  // col within head
            float as0 = as_h[cl_h], as1 = as_h[cl_h + 1];
            float ad0 = ad_h[cl_h], ad1 = ad_h[cl_h + 1];
            sl[mi * 2 + 0] += acc[mi][ni][0] * as0 + acc[mi][ni][1] * as1;
            sh_[mi * 2 + 0] += acc[mi][ni][0] * ad0 + acc[mi][ni][1] * ad1;
            sl[mi * 2 + 1] += acc[mi][ni][2] * as0 + acc[mi][ni][3] * as1;
            sh_[mi * 2 + 1] += acc[mi][ni][2] * ad0 + acc[mi][ni][3] * ad1;
            int c = n0 + wn * 32 + ni * 8 + (lane & 3) * 2;
            if (r0 < M) {
                __nv_bfloat162 p(__float2bfloat16(acc[mi][ni][0]), __float2bfloat16(acc[mi][ni][1]));
                *(__nv_bfloat162*)&C[(size_t)r0 * Nn + c] = p;
            }
            if (r0 + 8 < M) {
                __nv_bfloat162 p(__float2bfloat16(acc[mi][ni][2]), __float2bfloat16(acc[mi][ni][3]));
                *(__nv_bfloat162*)&C[(size_t)(r0 + 8) * Nn + c] = p;
            }
        }
    }
    #pragma unroll
    for (int off = 1; off <= 2; off <<= 1)
        #pragma unroll
        for (int i = 0; i < 8; i++) {
            sl[i] += __shfl_xor_sync(0xffffffffu, sl[i], off);
            sh_[i] += __shfl_xor_sync(0xffffffffu, sh_[i], off);
        }
    if ((lane & 3) == 0) {
        #pragma unroll
        for (int mi = 0; mi < 4; mi++) {
            int rl = wm * 64 + mi * 16 + (lane >> 2);
            atomicAdd(&s_alo[rl * 2 + head_local], sl[mi * 2]);
            atomicAdd(&s_ahi[rl * 2 + head_local], sh_[mi * 2]);
            atomicAdd(&s_alo[(rl + 8) * 2 + head_local], sl[mi * 2 + 1]);
            atomicAdd(&s_ahi[(rl + 8) * 2 + head_local], sh_[mi * 2 + 1]);
        }
    }
    __syncthreads();
    if (t < GBM && m0 + t < M) {
        alo[(m0 + t) * H + headbase + 0] = s_alo[t * 2 + 0];
        alo[(m0 + t) * H + headbase + 1] = s_alo[t * 2 + 1];
        ahi[(m0 + t) * H + headbase + 0] = s_ahi[t * 2 + 0];
        ahi[(m0 + t) * H + headbase + 1] = s_ahi[t * 2 + 1];
    }
}

// ---------------------------------------------------------------------------
// Narrow GEMM (layer 3): 128x64 tile, 8 warps (4m x 2n), warp 32x32.
// (round-13 proven kernel, verbatim)
// ---------------------------------------------------------------------------
__global__ __launch_bounds__(256) void k_gemm_bb(
    const __nv_bfloat16* __restrict__ A,
    const __nv_bfloat16* __restrict__ Bh, const __nv_bfloat16* __restrict__ Bl,
    __nv_bfloat16* __restrict__ C, int M, int Nn, int K,
    const float* __restrict__ a_src, const float* __restrict__ a_dst,
    float* __restrict__ alo, float* __restrict__ ahi, int H) {
    __shared__ __align__(16) unsigned int sA[GBM * WSTR];
    __shared__ __align__(16) unsigned int sBh[64 * WSTR], sBl[64 * WSTR];
    __shared__ float s_alo[GBM], s_ahi[GBM];

    int t = threadIdx.x;
    int lane = t & 31, warp = t >> 5;
    int wm = warp >> 1, wn = warp & 1;
    int m0 = blockIdx.y * GBM, n0 = blockIdx.x * 64;
    int head = blockIdx.x;

    if (t < GBM) { s_alo[t] = 0.f; s_ahi[t] = 0.f; }

    int arow = t >> 1, ahalf = t & 1;
    const __nv_bfloat16* pA = A + (size_t)(m0 + arow) * K + ahalf * 8;
    int wA = arow * WSTR + ahalf * 4;
    int u = t & 127;
    int brow = u >> 1, bhalf = u & 1;
    const __nv_bfloat16* pB = ((t < 128) ? Bh : Bl) + (size_t)(n0 + brow) * K + bhalf * 8;
    unsigned int* sB = (t < 128) ? sBh : sBl;
    int wB = brow * WSTR + bhalf * 4;

    unsigned int aBase = (unsigned int)__cvta_generic_to_shared(sA);
    unsigned int bHi = (unsigned int)__cvta_generic_to_shared(sBh);
    unsigned int bLo = (unsigned int)__cvta_generic_to_shared(sBl);
    unsigned int aAddr[2], bAddr[2], blAddr[2];
    #pragma unroll
    for (int mi = 0; mi < 2; mi++) {
        int r = wm * 32 + mi * 16 + (lane & 15);
        aAddr[mi] = aBase + (unsigned int)(r * WSTR * 4) + (((lane >> 4) & 1) * 16);
    }
    #pragma unroll
    for (int p = 0; p < 2; p++) {
        int r = wn * 32 + p * 16 + (((lane >> 4) & 1) * 8) + (lane & 7);
        unsigned int off = (unsigned int)(r * WSTR * 4) + (((lane >> 3) & 1) * 16);
        bAddr[p] = bHi + off; blAddr[p] = bLo + off;
    }

    float acc[2][4][4];
    #pragma unroll
    for (int i = 0; i < 2; i++)
        #pragma unroll
        for (int j = 0; j < 4; j++)
            #pragma unroll
            for (int k = 0; k < 4; k++) acc[i][j][k] = 0.f;

    for (int k0 = 0; k0 < K; k0 += GBK) {
        uint4 va = *(const uint4*)(pA + k0);
        uint4 vb = *(const uint4*)(pB + k0);
        *(uint4*)&sA[wA] = va;
        *(uint4*)&sB[wB] = vb;
        __syncthreads();

        unsigned int ah[2][4];
        ldsm_x4(ah[0], aAddr[0]);
        ldsm_x4(ah[1], aAddr[1]);
        unsigned int bq[4], blq[4];
        unsigned int bh[4][2], bl[4][2];
        ldsm_x4(bq, bAddr[0]);
        bh[0][0] = bq[0]; bh[0][1] = bq[1]; bh[1][0] = bq[2]; bh[1][1] = bq[3];
        ldsm_x4(bq, bAddr[1]);
        bh[2][0] = bq[0]; bh[2][1] = bq[1]; bh[3][0] = bq[2]; bh[3][1] = bq[3];
        ldsm_x4(blq, blAddr[0]);
        bl[0][0] = blq[0]; bl[0][1] = blq[1]; bl[1][0] = blq[2]; bl[1][1] = blq[3];
        ldsm_x4(blq, blAddr[1]);
        bl[2][0] = blq[0]; bl[2][1] = blq[1]; bl[3][0] = blq[2]; bl[3][1] = blq[3];

        #pragma unroll
        for (int mi = 0; mi < 2; mi++)
            #pragma unroll
            for (int ni = 0; ni < 4; ni++) {
                mma_bf16(acc[mi][ni], ah[mi], bh[ni]);
                mma_bf16(acc[mi][ni], ah[mi], bl[ni]);
            }
        __syncthreads();
    }

    const float* as_h = a_src + head * 64;
    const float* ad_h = a_dst + head * 64;
    float sl[4] = {0.f,0.f,0.f,0.f};
    float sh_[4] = {0.f,0.f,0.f,0.f};
    #pragma unroll
    for (int mi = 0; mi < 2; mi++) {
        int r0 = m0 + wm * 32 + mi * 16 + (lane >> 2);
        #pragma unroll
        for (int ni = 0; ni < 4; ni++) {
            int cl = wn * 32 + ni * 8 + (lane & 3) * 2;
            float as0 = as_h[cl], as1 = as_h[cl + 1];
            float ad0 = ad_h[cl], ad1 = ad_h[cl + 1];
            sl[mi * 2 + 0] += acc[mi][ni][0] * as0 + acc[mi][ni][1] * as1;
            sh_[mi * 2 + 0] += acc[mi][ni][0] * ad0 + acc[mi][ni][1] * ad1;
            sl[mi * 2 + 1] += acc[mi][ni][2] * as0 + acc[mi][ni][3] * as1;
            sh_[mi * 2 + 1] += acc[mi][ni][2] * ad0 + acc[mi][ni][3] * ad1;
            int c = n0 + cl;
            if (r0 < M) {
                __nv_bfloat162 p(__float2bfloat16(acc[mi][ni][0]), __float2bfloat16(acc[mi][ni][1]));
                *(__nv_bfloat162*)&C[(size_t)r0 * Nn + c] = p;
            }
            if (r0 + 8 < M) {
                __nv_bfloat162 p(__float2bfloat16(acc[mi][ni][2]), __float2bfloat16(acc[mi][ni][3]));
                *(__nv_bfloat162*)&C[(size_t)(r0 + 8) * Nn + c] = p;
            }
        }
    }
    #pragma unroll
    for (int off = 1; off <= 2; off <<= 1)
        #pragma unroll
        for (int i = 0; i < 4; i++) {
            sl[i] += __shfl_xor_sync(0xffffffffu, sl[i], off);
            sh_[i] += __shfl_xor_sync(0xffffffffu, sh_[i], off);
        }
    if ((lane & 3) == 0) {
        #pragma unroll
        for (int mi = 0; mi < 2; mi++) {
            int rl = wm * 32 + mi * 16 + (lane >> 2);
            atomicAdd(&s_alo[rl], sl[mi * 2]);
            atomicAdd(&s_ahi[rl], sh_[mi * 2]);
            atomicAdd(&s_alo[rl + 8], sl[mi * 2 + 1]);
            atomicAdd(&s_ahi[rl + 8], sh_[mi * 2 + 1]);
        }
    }
    __syncthreads();
    if (t < GBM && m0 + t < M) {
        alo[(m0 + t) * H + head] = s_alo[t];
        ahi[(m0 + t) * H + head] = s_ahi[t];
    }
}

// ---------------------------------------------------------------------------
// Packed f32x2 helpers
// ---------------------------------------------------------------------------
__device__ __forceinline__ unsigned long long pk2(unsigned int lo, unsigned int hi) {
    unsigned long long r;
    asm("mov.b64 %0, {%1,%2};" : "=l"(r) : "r"(lo), "r"(hi));
    return r;
}
__device__ __forceinline__ void ffma2(unsigned long long& acc, unsigned long long a, unsigned long long b) {
    asm("fma.rn.f32x2 %0, %1, %2, %0;" : "+l"(acc) : "l"(a), "l"(b));
}
__device__ __forceinline__ float2 upk2(unsigned long long v) {
    unsigned int lo, hi;
    asm("mov.b64 {%0,%1}, %2;" : "=r"(lo), "=r"(hi) : "l"(v));
    return make_float2(__uint_as_float(lo), __uint_as_float(hi));
}
__device__ __forceinline__ unsigned long long bf2f32x2(unsigned int r) {
    return pk2(r << 16, r & 0xffff0000u);
}

__device__ __forceinline__ float lrelu(float x) { return x > 0.f ? x : NEG_SLOPE * x; }

// ---------------------------------------------------------------------------
// Aggregation (layers 1/2, H=4): single-pass unnormalized softmax, bf16 out.
// ---------------------------------------------------------------------------
__global__ void k_aggregate4(const __nv_bfloat16* __restrict__ hw,
                             const float* __restrict__ alo,
                             const float* __restrict__ ahi,
                             const float* __restrict__ bias,
                             __nv_bfloat16* __restrict__ out) {
    const int H = 4, HCn = 256, FPL = 8;
    int warp = (blockIdx.x * blockDim.x + threadIdx.x) >> 5;
    int lane = threadIdx.x & 31;
    if (warp >= NNODES) return;
    int n = warp;
    int beg = g_off[n], deg = g_off[n + 1] - beg;

    int hh_l = lane >> 3;
    float my_a = ahi[n * H + hh_l];

    unsigned long long acc2[4] = {0ull, 0ull, 0ull, 0ull};
    float den = 0.f;

    const int total = deg + 1;
    int j = 0;
    for (; j + 1 < total; j += 2) {
        int s0 = g_csr[beg + j];
        int s1 = (j + 1 < deg) ? g_csr[beg + j + 1] : n;
        uint4 r0 = *(const uint4*)(hw + (size_t)s0 * HCn + lane * FPL);
        uint4 r1 = *(const uint4*)(hw + (size_t)s1 * HCn + lane * FPL);
        float w0 = __expf(lrelu(alo[s0 * H + hh_l] + my_a));
        float w1 = __expf(lrelu(alo[s1 * H + hh_l] + my_a));
        den += w0 + w1;
        unsigned long long w20 = pk2(__float_as_uint(w0), __float_as_uint(w0));
        unsigned long long w21 = pk2(__float_as_uint(w1), __float_as_uint(w1));
        ffma2(acc2[0], bf2f32x2(r0.x), w20);
        ffma2(acc2[1], bf2f32x2(r0.y), w20);
        ffma2(acc2[2], bf2f32x2(r0.z), w20);
        ffma2(acc2[3], bf2f32x2(r0.w), w20);
        ffma2(acc2[0], bf2f32x2(r1.x), w21);
        ffma2(acc2[1], bf2f32x2(r1.y), w21);
        ffma2(acc2[2], bf2f32x2(r1.z), w21);
        ffma2(acc2[3], bf2f32x2(r1.w), w21);
    }
    if (j < total) {
        int s = (j < deg) ? g_csr[beg + j] : n;
        uint4 r = *(const uint4*)(hw + (size_t)s * HCn + lane * FPL);
        float w = __expf(lrelu(alo[s * H + hh_l] + my_a));
        den += w;
        unsigned long long w2 = pk2(__float_as_uint(w), __float_as_uint(w));
        ffma2(acc2[0], bf2f32x2(r.x), w2);
        ffma2(acc2[1], bf2f32x2(r.y), w2);
        ffma2(acc2[2], bf2f32x2(r.z), w2);
        ffma2(acc2[3], bf2f32x2(r.w), w2);
    }
    float inv_d = 1.f / (den + 1e-16f);
    unsigned int wds[4];
    #pragma unroll
    for (int k = 0; k < 4; k++) {
        float2 a = upk2(acc2[k]);
        float v0 = a.x * inv_d + bias[lane * FPL + 2 * k];
        float v1 = a.y * inv_d + bias[lane * FPL + 2 * k + 1];
        v0 = (v0 > 0.f) ? v0 : expm1f(v0);
        v1 = (v1 > 0.f) ? v1 : expm1f(v1);
        wds[k] = cvt_bf16x2(v1, v0);
    }
    *(uint4*)(out + (size_t)n * HCn + lane * FPL) = make_uint4(wds[0], wds[1], wds[2], wds[3]);
}

// ---------------------------------------------------------------------------
// Layer-3 aggregation (H=1), single pass, fused with mean-pool accumulation.
// ---------------------------------------------------------------------------
__global__ void k_aggregate1_pool(const __nv_bfloat16* __restrict__ hw,
                                  const float* __restrict__ alo,
                                  const float* __restrict__ ahi,
                                  const float* __restrict__ bias,
                                  const int* __restrict__ batch) {
    const int HCn = 64, FPL = 2;
    int warp = (blockIdx.x * blockDim.x + threadIdx.x) >> 5;
    int lane = threadIdx.x & 31;
    if (warp >= NNODES) return;
    int n = warp;
    int beg = g_off[n], deg = g_off[n + 1] - beg;

    float ahin = ahi[n];
    float a0 = 0.f, a1 = 0.f, den = 0.f;
    const int total = deg + 1;
    int j = 0;
    for (; j + 1 < total; j += 2) {
        int s0 = g_csr[beg + j];
        int s1 = (j + 1 < deg) ? g_csr[beg + j + 1] : n;
        unsigned int r0 = *(const unsigned int*)(hw + (size_t)s0 * HCn + lane * FPL);
        unsigned int r1 = *(const unsigned int*)(hw + (size_t)s1 * HCn + lane * FPL);
        float w0 = __expf(lrelu(alo[s0] + ahin));
        float w1 = __expf(lrelu(alo[s1] + ahin));
        den += w0 + w1;
        float2 f0 = __bfloat1622float2(*(__nv_bfloat162*)&r0);
        float2 f1 = __bfloat1622float2(*(__nv_bfloat162*)&r1);
        a0 += w0 * f0.x + w1 * f1.x;
        a1 += w0 * f0.y + w1 * f1.y;
    }
    if (j < total) {
        int s = (j < deg) ? g_csr[beg + j] : n;
        unsigned int r = *(const unsigned int*)(hw + (size_t)s * HCn + lane * FPL);
        float w = __expf(lrelu(alo[s] + ahin));
        den += w;
        float2 f = __bfloat1622float2(*(__nv_bfloat162*)&r);
        a0 += w * f.x; a1 += w * f.y;
    }
    float inv_d = 1.f / (den + 1e-16f);
    float v0 = a0 * inv_d + bias[lane * FPL];
    float v1 = a1 * inv_d + bias[lane * FPL + 1];
    v0 = (v0 > 0.f) ? v0 : expm1f(v0);
    v1 = (v1 > 0.f) ? v1 : expm1f(v1);

    int b = batch[n];
    atomicAdd(&g_pool[b * HIDDEN + lane * FPL], v0);
    atomicAdd(&g_pool[b * HIDDEN + lane * FPL + 1], v1);
    if (lane == 0) atomicAdd(&g_cnt[b], 1.f);
}

// ---------------------------------------------------------------------------
// Heads MLP
// ---------------------------------------------------------------------------
__global__ void k_mlp(const float* __restrict__ Wc1, const float* __restrict__ bc1,
                      const float* __restrict__ Wc2, const float* __restrict__ bc2,
                      const float* __restrict__ Wr1, const float* __restrict__ br1,
                      const float* __restrict__ Wr2, const float* __restrict__ br2,
                      float* __restrict__ out) {
    int warp = (blockIdx.x * blockDim.x + threadIdx.x) >> 5;
    int lane = threadIdx.x & 31;
    if (warp >= NGRAPHS) return;
    float inv_cnt = 1.f / fmaxf(g_cnt[warp], 1.f);
    const float* gp = &g_pool[warp * HIDDEN];

    {
        float h0 = bc1[lane], h1 = bc1[lane + 32];
        for (int c = 0; c < HIDDEN; c++) {
            float gc = gp[c] * inv_cnt;
            h0 += Wc1[lane * HIDDEN + c] * gc;
            h1 += Wc1[(lane + 32) * HIDDEN + c] * gc;
        }
        h0 = fmaxf(h0, 0.f); h1 = fmaxf(h1, 0.f);
        float s = Wc2[lane] * h0 + Wc2[lane + 32] * h1;
        #pragma unroll
        for (int off = 16; off > 0; off >>= 1) s += __shfl_xor_sync(0xffffffffu, s, off);
        if (lane == 0) out[warp] = s + bc2[0];
    }
    {
        float h0 = br1[lane], h1 = br1[lane + 32];
        for (int c = 0; c < HIDDEN; c++) {
            float gc = gp[c] * inv_cnt;
            h0 += Wr1[lane * HIDDEN + c] * gc;
            h1 += Wr1[(lane + 32) * HIDDEN + c] * gc;
        }
        h0 = fmaxf(h0, 0.f); h1 = fmaxf(h1, 0.f);
        float s = Wr2[lane] * h0 + Wr2[lane + 32] * h1;
        #pragma unroll
        for (int off = 16; off > 0; off >>= 1) s += __shfl_xor_sync(0xffffffffu, s, off);
        if (lane == 0) out[NGRAPHS + warp] = s + br2[0];
    }
}

// ---------------------------------------------------------------------------
// Launch (6th launch = k_aggregate4 -> lands in ncu's skip-5 window)
// ---------------------------------------------------------------------------
extern "C" void kernel_launch(void* const* d_in, const int* in_sizes, int n_in,
                              void* d_out, int out_size) {
    const float* x     = (const float*)d_in[0];
    const int*   ei    = (const int*)d_in[1];
    const int*   batch = (const int*)d_in[2];
    const float* W1  = (const float*)d_in[3];
    const float* as1 = (const float*)d_in[4];
    const float* ad1 = (const float*)d_in[5];
    const float* b1  = (const float*)d_in[6];
    const float* W2  = (const float*)d_in[7];
    const float* as2 = (const float*)d_in[8];
    const float* ad2 = (const float*)d_in[9];
    const float* b2  = (const float*)d_in[10];
    const float* W3  = (const float*)d_in[11];
    const float* as3 = (const float*)d_in[12];
    const float* ad3 = (const float*)d_in[13];
    const float* b3  = (const float*)d_in[14];
    const float* Wc1 = (const float*)d_in[15];
    const float* bc1 = (const float*)d_in[16];
    const float* Wc2 = (const float*)d_in[17];
    const float* bc2 = (const float*)d_in[18];
    const float* Wr1 = (const float*)d_in[19];
    const float* br1 = (const float*)d_in[20];
    const float* Wr2 = (const float*)d_in[21];
    const float* br2 = (const float*)d_in[22];
    float* out = (float*)d_out;

    const int* srcp = ei;
    const int* dstp = ei + NEDGES;

    __nv_bfloat16 *hw_p, *xbf_p, *featb_p, *w1h_p, *w1l_p, *w2h_p, *w2l_p, *w3h_p, *w3l_p;
    cudaGetSymbolAddress((void**)&hw_p,    g_hw);
    cudaGetSymbolAddress((void**)&xbf_p,   g_xbf);
    cudaGetSymbolAddress((void**)&featb_p, g_featb);
    cudaGetSymbolAddress((void**)&w1h_p,   g_W1h);
    cudaGetSymbolAddress((void**)&w1l_p,   g_W1l);
    cudaGetSymbolAddress((void**)&w2h_p,   g_W2h);
    cudaGetSymbolAddress((void**)&w2l_p,   g_W2l);
    cudaGetSymbolAddress((void**)&w3h_p,   g_W3h);
    cudaGetSymbolAddress((void**)&w3l_p,   g_W3l);
    float *alo_p, *ahi_p;
    cudaGetSymbolAddress((void**)&alo_p, g_alo);
    cudaGetSymbolAddress((void**)&ahi_p, g_ahi);

    const int warps_grid = (NNODES * 32 + 255) / 256;
    const int mblocks = (NNODES + GBM - 1) / GBM;

    k_zero_csr<<<(NNODES + 256) / 256, 256>>>();
    k_pre<<<(NNODES * IN_DIM / 2 + 255) / 256, 256>>>(x, W1, W2, W3, dstp);
    k_scan<<<1, 1024>>>();
    k_gemm_w<<<dim3(HC1 / 128, mblocks), 256>>>(xbf_p, w1h_p, w1l_p, hw_p, NNODES, HC1, IN_DIM,
                                                as1, ad1, alo_p, ahi_p, HEADS);
    k_scatter<<<(NEDGES + 255) / 256, 256>>>(srcp, dstp);

    k_aggregate4<<<warps_grid, 256>>>(hw_p, alo_p, ahi_p, b1, featb_p);
    k_gemm_w<<<dim3(HC1 / 128, mblocks), 256>>>(featb_p, w2h_p, w2l_p, hw_p, NNODES, HC1, HC1,
                                                as2, ad2, alo_p, ahi_p, HEADS);
    k_aggregate4<<<warps_grid, 256>>>(hw_p, alo_p, ahi_p, b2, featb_p);
    k_gemm_bb<<<dim3(1, mblocks), 256>>>(featb_p, w3h_p, w3l_p, hw_p, NNODES, HIDDEN, HC1,
                                         as3, ad3, alo_p, ahi_p, 1);
    k_aggregate1_pool<<<warps_grid, 256>>>(hw_p, alo_p, ahi_p, b3, batch);

    k_mlp<<<(NGRAPHS * 32 + 255) / 256, 256>>>(Wc1, bc1, Wc2, bc2, Wr1, br1, Wr2, br2, out);
}

// round 16
// speedup vs baseline: 1.0935x; 1.0654x over previous
#include <cuda_runtime.h>
#include <cuda_bf16.h>
#include <stdint.h>
#include <math.h>

// ---------------------------------------------------------------------------
// Problem constants
// ---------------------------------------------------------------------------
#define NNODES   50000
#define NEDGES   800000
#define IN_DIM   128
#define HIDDEN   64
#define HEADS    4
#define NGRAPHS  256
#define HC1      256
#define NEG_SLOPE 0.2f

#define GBM 128
#define GBK 16
#define WSTR 12

// ---------------------------------------------------------------------------
// Device scratch (node-feature buffers padded by one m-tile)
// ---------------------------------------------------------------------------
__device__ __nv_bfloat16 g_hw[(size_t)NNODES * HC1];
__device__ __nv_bfloat16 g_xbf[(size_t)(NNODES + GBM) * IN_DIM];
__device__ __nv_bfloat16 g_featb[(size_t)(NNODES + GBM) * HC1];
__device__ __nv_bfloat16 g_W1h[HC1 * IN_DIM], g_W1l[HC1 * IN_DIM];
__device__ __nv_bfloat16 g_W2h[HC1 * HC1],   g_W2l[HC1 * HC1];
__device__ __nv_bfloat16 g_W3h[HIDDEN * HC1], g_W3l[HIDDEN * HC1];
__device__ float g_alo[NNODES * HEADS];
__device__ float g_ahi[NNODES * HEADS];
__device__ int   g_off[NNODES + 1];
__device__ int   g_fill[NNODES];
__device__ int   g_csr[NEDGES];
__device__ float g_pool[NGRAPHS * HIDDEN];
__device__ float g_cnt[NGRAPHS];

// ---------------------------------------------------------------------------
// cp.async helpers
// ---------------------------------------------------------------------------
__device__ __forceinline__ void cp16(unsigned int saddr, const void* gptr) {
    asm volatile("cp.async.cg.shared.global [%0], [%1], 16;" :: "r"(saddr), "l"(gptr) : "memory");
}
__device__ __forceinline__ void cp_commit_wait() {
    asm volatile("cp.async.commit_group;\ncp.async.wait_group 0;" ::: "memory");
}

// ---------------------------------------------------------------------------
// Zero kernel (must precede hist)
// ---------------------------------------------------------------------------
__global__ void k_zero_csr() {
    int i = blockIdx.x * blockDim.x + threadIdx.x;
    if (i <= NNODES) g_off[i] = 0;
    if (i < NGRAPHS * HIDDEN) g_pool[i] = 0.f;
    if (i < NGRAPHS) g_cnt[i] = 0.f;
}

// ---------------------------------------------------------------------------
// Fused pre-pass: x->bf16, weight split, dst histogram
// ---------------------------------------------------------------------------
__global__ void k_pre(const float* __restrict__ x,
                      const float* __restrict__ W1, const float* __restrict__ W2,
                      const float* __restrict__ W3, const int* __restrict__ dst) {
    int i = blockIdx.x * blockDim.x + threadIdx.x;
    if (i < NNODES * IN_DIM / 2) {
        float2 v = ((const float2*)x)[i];
        __nv_bfloat162 p(__float2bfloat16(v.x), __float2bfloat16(v.y));
        ((__nv_bfloat162*)g_xbf)[i] = p;
    }
    if (i < NEDGES) atomicAdd(&g_off[dst[i] + 1], 1);
    const int S1 = HC1 * IN_DIM, S2 = HC1 * HC1, S3 = HIDDEN * HC1;
    if (i < S1 + S2 + S3) {
        const float* src; __nv_bfloat16 *dh, *dl; int idx;
        if (i < S1)           { src = W1; dh = g_W1h; dl = g_W1l; idx = i; }
        else if (i < S1 + S2) { src = W2; dh = g_W2h; dl = g_W2l; idx = i - S1; }
        else                  { src = W3; dh = g_W3h; dl = g_W3l; idx = i - S1 - S2; }
        float w = src[idx];
        unsigned int b = __float_as_uint(w);
        float hi = __uint_as_float(b & 0xffff0000u);
        __nv_bfloat16 h; *(unsigned short*)&h = (unsigned short)(b >> 16);
        dh[idx] = h;
        dl[idx] = __float2bfloat16(w - hi);
    }
}

__global__ void k_scan() {
    __shared__ int wsum[32];
    __shared__ int carry;
    int t = threadIdx.x, lane = t & 31, wid = t >> 5;
    if (t == 0) carry = 0;
    __syncthreads();
    for (int base = 0; base < NNODES; base += 1024) {
        int i = base + t;
        int cnt = (i < NNODES) ? g_off[i + 1] : 0;
        int v = cnt;
        #pragma unroll
        for (int off = 1; off < 32; off <<= 1) {
            int nb = __shfl_up_sync(0xffffffffu, v, off);
            if (lane >= off) v += nb;
        }
        if (lane == 31) wsum[wid] = v;
        __syncthreads();
        if (wid == 0) {
            int s = wsum[lane];
            #pragma unroll
            for (int off = 1; off < 32; off <<= 1) {
                int nb = __shfl_up_sync(0xffffffffu, s, off);
                if (lane >= off) s += nb;
            }
            wsum[lane] = s;
        }
        __syncthreads();
        int add = carry + (wid > 0 ? wsum[wid - 1] : 0);
        int inc = v + add;
        if (i < NNODES) { g_off[i + 1] = inc; g_fill[i] = inc - cnt; }
        __syncthreads();
        if (t == 0) carry += wsum[31];
        __syncthreads();
    }
}

__global__ void k_scatter(const int* __restrict__ src, const int* __restrict__ dst) {
    int e = blockIdx.x * blockDim.x + threadIdx.x;
    if (e < NEDGES) {
        int p = atomicAdd(&g_fill[dst[e]], 1);
        g_csr[p] = src[e];
    }
}

// ---------------------------------------------------------------------------
// GEMM helpers
// ---------------------------------------------------------------------------
__device__ __forceinline__ void mma_bf16(float* d, const unsigned int* a, const unsigned int* b) {
    asm volatile(
        "mma.sync.aligned.m16n8k16.row.col.f32.bf16.bf16.f32 "
        "{%0,%1,%2,%3}, {%4,%5,%6,%7}, {%8,%9}, {%0,%1,%2,%3};\n"
        : "+f"(d[0]), "+f"(d[1]), "+f"(d[2]), "+f"(d[3])
        : "r"(a[0]), "r"(a[1]), "r"(a[2]), "r"(a[3]), "r"(b[0]), "r"(b[1]));
}

__device__ __forceinline__ void ldsm_x4(unsigned int* r, unsigned int addr) {
    asm volatile("ldmatrix.sync.aligned.m8n8.x4.shared.b16 {%0,%1,%2,%3}, [%4];"
        : "=r"(r[0]), "=r"(r[1]), "=r"(r[2]), "=r"(r[3]) : "r"(addr));
}

__device__ __forceinline__ unsigned int cvt_bf16x2(float hi, float lo) {
    unsigned int r; asm("cvt.rn.bf16x2.f32 %0, %1, %2;" : "=r"(r) : "f"(hi), "f"(lo)); return r;
}

// ---------------------------------------------------------------------------
// Wide GEMM (layers 1-2): 128x128 tile, 256 threads, 8 warps (2m x 4n),
// warp tile 64x32. A plain bf16, B split. cp.async fills, 2 CTAs/SM.
// ---------------------------------------------------------------------------
__global__ __launch_bounds__(256, 2) void k_gemm_w(
    const __nv_bfloat16* __restrict__ A,
    const __nv_bfloat16* __restrict__ Bh, const __nv_bfloat16* __restrict__ Bl,
    __nv_bfloat16* __restrict__ C, int M, int Nn, int K,
    const float* __restrict__ a_src, const float* __restrict__ a_dst,
    float* __restrict__ alo, float* __restrict__ ahi, int H) {
    __shared__ __align__(16) unsigned int sA[GBM * WSTR];
    __shared__ __align__(16) unsigned int sBh[128 * WSTR], sBl[128 * WSTR];
    __shared__ float s_alo[GBM * 2], s_ahi[GBM * 2];

    int t = threadIdx.x;
    int lane = t & 31, warp = t >> 5;
    int wm = warp >> 2, wn = warp & 3;          // 2m x 4n
    int m0 = blockIdx.y * GBM, n0 = blockIdx.x * 128;
    int headbase = blockIdx.x * 2;
    int head_local = wn >> 1;

    if (t < GBM * 2) { s_alo[t] = 0.f; s_ahi[t] = 0.f; }

    int row = t >> 1, half = t & 1;
    const __nv_bfloat16* pA  = A  + (size_t)(m0 + row) * K + half * 8;
    const __nv_bfloat16* pBh = Bh + (size_t)(n0 + row) * K + half * 8;
    const __nv_bfloat16* pBl = Bl + (size_t)(n0 + row) * K + half * 8;
    int wI = row * WSTR + half * 4;

    unsigned int aBase = (unsigned int)__cvta_generic_to_shared(sA);
    unsigned int bHi = (unsigned int)__cvta_generic_to_shared(sBh);
    unsigned int bLo = (unsigned int)__cvta_generic_to_shared(sBl);
    unsigned int fillA  = aBase + wI * 4;
    unsigned int fillBh = bHi + wI * 4;
    unsigned int fillBl = bLo + wI * 4;

    unsigned int aAddr[4], bAddr[2], blAddr[2];
    #pragma unroll
    for (int mi = 0; mi < 4; mi++) {
        int r = wm * 64 + mi * 16 + (lane & 15);
        aAddr[mi] = aBase + (unsigned int)(r * WSTR * 4) + (((lane >> 4) & 1) * 16);
    }
    #pragma unroll
    for (int p = 0; p < 2; p++) {
        int r = wn * 32 + p * 16 + (((lane >> 4) & 1) * 8) + (lane & 7);
        unsigned int off = (unsigned int)(r * WSTR * 4) + (((lane >> 3) & 1) * 16);
        bAddr[p] = bHi + off; blAddr[p] = bLo + off;
    }

    float acc[4][4][4];
    #pragma unroll
    for (int i = 0; i < 4; i++)
        #pragma unroll
        for (int j = 0; j < 4; j++)
            #pragma unroll
            for (int k = 0; k < 4; k++) acc[i][j][k] = 0.f;

    for (int k0 = 0; k0 < K; k0 += GBK) {
        cp16(fillA,  pA + k0);
        cp16(fillBh, pBh + k0);
        cp16(fillBl, pBl + k0);
        cp_commit_wait();
        __syncthreads();

        unsigned int ah[4][4];
        ldsm_x4(ah[0], aAddr[0]);
        ldsm_x4(ah[1], aAddr[1]);
        ldsm_x4(ah[2], aAddr[2]);
        ldsm_x4(ah[3], aAddr[3]);
        unsigned int bq[4], blq[4];
        unsigned int bh[4][2], bl[4][2];
        ldsm_x4(bq, bAddr[0]);
        bh[0][0] = bq[0]; bh[0][1] = bq[1]; bh[1][0] = bq[2]; bh[1][1] = bq[3];
        ldsm_x4(bq, bAddr[1]);
        bh[2][0] = bq[0]; bh[2][1] = bq[1]; bh[3][0] = bq[2]; bh[3][1] = bq[3];
        ldsm_x4(blq, blAddr[0]);
        bl[0][0] = blq[0]; bl[0][1] = blq[1]; bl[1][0] = blq[2]; bl[1][1] = blq[3];
        ldsm_x4(blq, blAddr[1]);
        bl[2][0] = blq[0]; bl[2][1] = blq[1]; bl[3][0] = blq[2]; bl[3][1] = blq[3];

        #pragma unroll
        for (int mi = 0; mi < 4; mi++)
            #pragma unroll
            for (int ni = 0; ni < 4; ni++) {
                mma_bf16(acc[mi][ni], ah[mi], bh[ni]);
                mma_bf16(acc[mi][ni], ah[mi], bl[ni]);
            }
        __syncthreads();
    }

    // ---- epilogue: bf16 C store + fused alo/ahi (per-head) ----
    const float* as_h = a_src + (headbase + head_local) * 64;
    const float* ad_h = a_dst + (headbase + head_local) * 64;
    float sl[8], sh_[8];
    #pragma unroll
    for (int i = 0; i < 8; i++) { sl[i] = 0.f; sh_[i] = 0.f; }
    #pragma unroll
    for (int mi = 0; mi < 4; mi++) {
        int r0 = m0 + wm * 64 + mi * 16 + (lane >> 2);
        #pragma unroll
        for (int ni = 0; ni < 4; ni++) {
            int cl_h = (wn & 1) * 32 + ni * 8 + (lane & 3) * 2;
            float as0 = as_h[cl_h], as1 = as_h[cl_h + 1];
            float ad0 = ad_h[cl_h], ad1 = ad_h[cl_h + 1];
            sl[mi * 2 + 0] += acc[mi][ni][0] * as0 + acc[mi][ni][1] * as1;
            sh_[mi * 2 + 0] += acc[mi][ni][0] * ad0 + acc[mi][ni][1] * ad1;
            sl[mi * 2 + 1] += acc[mi][ni][2] * as0 + acc[mi][ni][3] * as1;
            sh_[mi * 2 + 1] += acc[mi][ni][2] * ad0 + acc[mi][ni][3] * ad1;
            int c = n0 + wn * 32 + ni * 8 + (lane & 3) * 2;
            if (r0 < M) {
                __nv_bfloat162 p(__float2bfloat16(acc[mi][ni][0]), __float2bfloat16(acc[mi][ni][1]));
                *(__nv_bfloat162*)&C[(size_t)r0 * Nn + c] = p;
            }
            if (r0 + 8 < M) {
                __nv_bfloat162 p(__float2bfloat16(acc[mi][ni][2]), __float2bfloat16(acc[mi][ni][3]));
                *(__nv_bfloat162*)&C[(size_t)(r0 + 8) * Nn + c] = p;
            }
        }
    }
    #pragma unroll
    for (int off = 1; off <= 2; off <<= 1)
        #pragma unroll
        for (int i = 0; i < 8; i++) {
            sl[i] += __shfl_xor_sync(0xffffffffu, sl[i], off);
            sh_[i] += __shfl_xor_sync(0xffffffffu, sh_[i], off);
        }
    if ((lane & 3) == 0) {
        #pragma unroll
        for (int mi = 0; mi < 4; mi++) {
            int rl = wm * 64 + mi * 16 + (lane >> 2);
            atomicAdd(&s_alo[rl * 2 + head_local], sl[mi * 2]);
            atomicAdd(&s_ahi[rl * 2 + head_local], sh_[mi * 2]);
            atomicAdd(&s_alo[(rl + 8) * 2 + head_local], sl[mi * 2 + 1]);
            atomicAdd(&s_ahi[(rl + 8) * 2 + head_local], sh_[mi * 2 + 1]);
        }
    }
    __syncthreads();
    if (t < GBM && m0 + t < M) {
        alo[(m0 + t) * H + headbase + 0] = s_alo[t * 2 + 0];
        alo[(m0 + t) * H + headbase + 1] = s_alo[t * 2 + 1];
        ahi[(m0 + t) * H + headbase + 0] = s_ahi[t * 2 + 0];
        ahi[(m0 + t) * H + headbase + 1] = s_ahi[t * 2 + 1];
    }
}

// ---------------------------------------------------------------------------
// Narrow GEMM (layer 3): 128x64 tile, 8 warps (4m x 2n), warp 32x32.
// cp.async fills.
// ---------------------------------------------------------------------------
__global__ __launch_bounds__(256) void k_gemm_bb(
    const __nv_bfloat16* __restrict__ A,
    const __nv_bfloat16* __restrict__ Bh, const __nv_bfloat16* __restrict__ Bl,
    __nv_bfloat16* __restrict__ C, int M, int Nn, int K,
    const float* __restrict__ a_src, const float* __restrict__ a_dst,
    float* __restrict__ alo, float* __restrict__ ahi, int H) {
    __shared__ __align__(16) unsigned int sA[GBM * WSTR];
    __shared__ __align__(16) unsigned int sBh[64 * WSTR], sBl[64 * WSTR];
    __shared__ float s_alo[GBM], s_ahi[GBM];

    int t = threadIdx.x;
    int lane = t & 31, warp = t >> 5;
    int wm = warp >> 1, wn = warp & 1;
    int m0 = blockIdx.y * GBM, n0 = blockIdx.x * 64;
    int head = blockIdx.x;

    if (t < GBM) { s_alo[t] = 0.f; s_ahi[t] = 0.f; }

    int arow = t >> 1, ahalf = t & 1;
    const __nv_bfloat16* pA = A + (size_t)(m0 + arow) * K + ahalf * 8;
    int wA = arow * WSTR + ahalf * 4;
    int u = t & 127;
    int brow = u >> 1, bhalf = u & 1;
    const __nv_bfloat16* pB = ((t < 128) ? Bh : Bl) + (size_t)(n0 + brow) * K + bhalf * 8;
    unsigned int* sB = (t < 128) ? sBh : sBl;
    int wB = brow * WSTR + bhalf * 4;

    unsigned int aBase = (unsigned int)__cvta_generic_to_shared(sA);
    unsigned int bHi = (unsigned int)__cvta_generic_to_shared(sBh);
    unsigned int bLo = (unsigned int)__cvta_generic_to_shared(sBl);
    unsigned int fillA = aBase + wA * 4;
    unsigned int fillB = (unsigned int)__cvta_generic_to_shared(sB) + wB * 4;

    unsigned int aAddr[2], bAddr[2], blAddr[2];
    #pragma unroll
    for (int mi = 0; mi < 2; mi++) {
        int r = wm * 32 + mi * 16 + (lane & 15);
        aAddr[mi] = aBase + (unsigned int)(r * WSTR * 4) + (((lane >> 4) & 1) * 16);
    }
    #pragma unroll
    for (int p = 0; p < 2; p++) {
        int r = wn * 32 + p * 16 + (((lane >> 4) & 1) * 8) + (lane & 7);
        unsigned int off = (unsigned int)(r * WSTR * 4) + (((lane >> 3) & 1) * 16);
        bAddr[p] = bHi + off; blAddr[p] = bLo + off;
    }

    float acc[2][4][4];
    #pragma unroll
    for (int i = 0; i < 2; i++)
        #pragma unroll
        for (int j = 0; j < 4; j++)
            #pragma unroll
            for (int k = 0; k < 4; k++) acc[i][j][k] = 0.f;

    for (int k0 = 0; k0 < K; k0 += GBK) {
        cp16(fillA, pA + k0);
        cp16(fillB, pB + k0);
        cp_commit_wait();
        __syncthreads();

        unsigned int ah[2][4];
        ldsm_x4(ah[0], aAddr[0]);
        ldsm_x4(ah[1], aAddr[1]);
        unsigned int bq[4], blq[4];
        unsigned int bh[4][2], bl[4][2];
        ldsm_x4(bq, bAddr[0]);
        bh[0][0] = bq[0]; bh[0][1] = bq[1]; bh[1][0] = bq[2]; bh[1][1] = bq[3];
        ldsm_x4(bq, bAddr[1]);
        bh[2][0] = bq[0]; bh[2][1] = bq[1]; bh[3][0] = bq[2]; bh[3][1] = bq[3];
        ldsm_x4(blq, blAddr[0]);
        bl[0][0] = blq[0]; bl[0][1] = blq[1]; bl[1][0] = blq[2]; bl[1][1] = blq[3];
        ldsm_x4(blq, blAddr[1]);
        bl[2][0] = blq[0]; bl[2][1] = blq[1]; bl[3][0] = blq[2]; bl[3][1] = blq[3];

        #pragma unroll
        for (int mi = 0; mi < 2; mi++)
            #pragma unroll
            for (int ni = 0; ni < 4; ni++) {
                mma_bf16(acc[mi][ni], ah[mi], bh[ni]);
                mma_bf16(acc[mi][ni], ah[mi], bl[ni]);
            }
        __syncthreads();
    }

    const float* as_h = a_src + head * 64;
    const float* ad_h = a_dst + head * 64;
    float sl[4] = {0.f,0.f,0.f,0.f};
    float sh_[4] = {0.f,0.f,0.f,0.f};
    #pragma unroll
    for (int mi = 0; mi < 2; mi++) {
        int r0 = m0 + wm * 32 + mi * 16 + (lane >> 2);
        #pragma unroll
        for (int ni = 0; ni < 4; ni++) {
            int cl = wn * 32 + ni * 8 + (lane & 3) * 2;
            float as0 = as_h[cl], as1 = as_h[cl + 1];
            float ad0 = ad_h[cl], ad1 = ad_h[cl + 1];
            sl[mi * 2 + 0] += acc[mi][ni][0] * as0 + acc[mi][ni][1] * as1;
            sh_[mi * 2 + 0] += acc[mi][ni][0] * ad0 + acc[mi][ni][1] * ad1;
            sl[mi * 2 + 1] += acc[mi][ni][2] * as0 + acc[mi][ni][3] * as1;
            sh_[mi * 2 + 1] += acc[mi][ni][2] * ad0 + acc[mi][ni][3] * ad1;
            int c = n0 + cl;
            if (r0 < M) {
                __nv_bfloat162 p(__float2bfloat16(acc[mi][ni][0]), __float2bfloat16(acc[mi][ni][1]));
                *(__nv_bfloat162*)&C[(size_t)r0 * Nn + c] = p;
            }
            if (r0 + 8 < M) {
                __nv_bfloat162 p(__float2bfloat16(acc[mi][ni][2]), __float2bfloat16(acc[mi][ni][3]));
                *(__nv_bfloat162*)&C[(size_t)(r0 + 8) * Nn + c] = p;
            }
        }
    }
    #pragma unroll
    for (int off = 1; off <= 2; off <<= 1)
        #pragma unroll
        for (int i = 0; i < 4; i++) {
            sl[i] += __shfl_xor_sync(0xffffffffu, sl[i], off);
            sh_[i] += __shfl_xor_sync(0xffffffffu, sh_[i], off);
        }
    if ((lane & 3) == 0) {
        #pragma unroll
        for (int mi = 0; mi < 2; mi++) {
            int rl = wm * 32 + mi * 16 + (lane >> 2);
            atomicAdd(&s_alo[rl], sl[mi * 2]);
            atomicAdd(&s_ahi[rl], sh_[mi * 2]);
            atomicAdd(&s_alo[rl + 8], sl[mi * 2 + 1]);
            atomicAdd(&s_ahi[rl + 8], sh_[mi * 2 + 1]);
        }
    }
    __syncthreads();
    if (t < GBM && m0 + t < M) {
        alo[(m0 + t) * H + head] = s_alo[t];
        ahi[(m0 + t) * H + head] = s_ahi[t];
    }
}

// ---------------------------------------------------------------------------
// Packed f32x2 helpers
// ---------------------------------------------------------------------------
__device__ __forceinline__ unsigned long long pk2(unsigned int lo, unsigned int hi) {
    unsigned long long r;
    asm("mov.b64 %0, {%1,%2};" : "=l"(r) : "r"(lo), "r"(hi));
    return r;
}
__device__ __forceinline__ void ffma2(unsigned long long& acc, unsigned long long a, unsigned long long b) {
    asm("fma.rn.f32x2 %0, %1, %2, %0;" : "+l"(acc) : "l"(a), "l"(b));
}
__device__ __forceinline__ float2 upk2(unsigned long long v) {
    unsigned int lo, hi;
    asm("mov.b64 {%0,%1}, %2;" : "=r"(lo), "=r"(hi) : "l"(v));
    return make_float2(__uint_as_float(lo), __uint_as_float(hi));
}
__device__ __forceinline__ unsigned long long bf2f32x2(unsigned int r) {
    return pk2(r << 16, r & 0xffff0000u);
}

__device__ __forceinline__ float lrelu(float x) { return x > 0.f ? x : NEG_SLOPE * x; }

// ---------------------------------------------------------------------------
// Aggregation (layers 1/2, H=4): single-pass unnormalized softmax, bf16 out.
// ---------------------------------------------------------------------------
__global__ void k_aggregate4(const __nv_bfloat16* __restrict__ hw,
                             const float* __restrict__ alo,
                             const float* __restrict__ ahi,
                             const float* __restrict__ bias,
                             __nv_bfloat16* __restrict__ out) {
    const int H = 4, HCn = 256, FPL = 8;
    int warp = (blockIdx.x * blockDim.x + threadIdx.x) >> 5;
    int lane = threadIdx.x & 31;
    if (warp >= NNODES) return;
    int n = warp;
    int beg = g_off[n], deg = g_off[n + 1] - beg;

    int hh_l = lane >> 3;
    float my_a = ahi[n * H + hh_l];

    unsigned long long acc2[4] = {0ull, 0ull, 0ull, 0ull};
    float den = 0.f;

    const int total = deg + 1;
    int j = 0;
    for (; j + 1 < total; j += 2) {
        int s0 = g_csr[beg + j];
        int s1 = (j + 1 < deg) ? g_csr[beg + j + 1] : n;
        uint4 r0 = *(const uint4*)(hw + (size_t)s0 * HCn + lane * FPL);
        uint4 r1 = *(const uint4*)(hw + (size_t)s1 * HCn + lane * FPL);
        float w0 = __expf(lrelu(alo[s0 * H + hh_l] + my_a));
        float w1 = __expf(lrelu(alo[s1 * H + hh_l] + my_a));
        den += w0 + w1;
        unsigned long long w20 = pk2(__float_as_uint(w0), __float_as_uint(w0));
        unsigned long long w21 = pk2(__float_as_uint(w1), __float_as_uint(w1));
        ffma2(acc2[0], bf2f32x2(r0.x), w20);
        ffma2(acc2[1], bf2f32x2(r0.y), w20);
        ffma2(acc2[2], bf2f32x2(r0.z), w20);
        ffma2(acc2[3], bf2f32x2(r0.w), w20);
        ffma2(acc2[0], bf2f32x2(r1.x), w21);
        ffma2(acc2[1], bf2f32x2(r1.y), w21);
        ffma2(acc2[2], bf2f32x2(r1.z), w21);
        ffma2(acc2[3], bf2f32x2(r1.w), w21);
    }
    if (j < total) {
        int s = (j < deg) ? g_csr[beg + j] : n;
        uint4 r = *(const uint4*)(hw + (size_t)s * HCn + lane * FPL);
        float w = __expf(lrelu(alo[s * H + hh_l] + my_a));
        den += w;
        unsigned long long w2 = pk2(__float_as_uint(w), __float_as_uint(w));
        ffma2(acc2[0], bf2f32x2(r.x), w2);
        ffma2(acc2[1], bf2f32x2(r.y), w2);
        ffma2(acc2[2], bf2f32x2(r.z), w2);
        ffma2(acc2[3], bf2f32x2(r.w), w2);
    }
    float inv_d = 1.f / (den + 1e-16f);
    unsigned int wds[4];
    #pragma unroll
    for (int k = 0; k < 4; k++) {
        float2 a = upk2(acc2[k]);
        float v0 = a.x * inv_d + bias[lane * FPL + 2 * k];
        float v1 = a.y * inv_d + bias[lane * FPL + 2 * k + 1];
        v0 = (v0 > 0.f) ? v0 : expm1f(v0);
        v1 = (v1 > 0.f) ? v1 : expm1f(v1);
        wds[k] = cvt_bf16x2(v1, v0);
    }
    *(uint4*)(out + (size_t)n * HCn + lane * FPL) = make_uint4(wds[0], wds[1], wds[2], wds[3]);
}

// ---------------------------------------------------------------------------
// Layer-3 aggregation (H=1), single pass, fused with mean-pool accumulation.
// ---------------------------------------------------------------------------
__global__ void k_aggregate1_pool(const __nv_bfloat16* __restrict__ hw,
                                  const float* __restrict__ alo,
                                  const float* __restrict__ ahi,
                                  const float* __restrict__ bias,
                                  const int* __restrict__ batch) {
    const int HCn = 64, FPL = 2;
    int warp = (blockIdx.x * blockDim.x + threadIdx.x) >> 5;
    int lane = threadIdx.x & 31;
    if (warp >= NNODES) return;
    int n = warp;
    int beg = g_off[n], deg = g_off[n + 1] - beg;

    float ahin = ahi[n];
    float a0 = 0.f, a1 = 0.f, den = 0.f;
    const int total = deg + 1;
    int j = 0;
    for (; j + 1 < total; j += 2) {
        int s0 = g_csr[beg + j];
        int s1 = (j + 1 < deg) ? g_csr[beg + j + 1] : n;
        unsigned int r0 = *(const unsigned int*)(hw + (size_t)s0 * HCn + lane * FPL);
        unsigned int r1 = *(const unsigned int*)(hw + (size_t)s1 * HCn + lane * FPL);
        float w0 = __expf(lrelu(alo[s0] + ahin));
        float w1 = __expf(lrelu(alo[s1] + ahin));
        den += w0 + w1;
        float2 f0 = __bfloat1622float2(*(__nv_bfloat162*)&r0);
        float2 f1 = __bfloat1622float2(*(__nv_bfloat162*)&r1);
        a0 += w0 * f0.x + w1 * f1.x;
        a1 += w0 * f0.y + w1 * f1.y;
    }
    if (j < total) {
        int s = (j < deg) ? g_csr[beg + j] : n;
        unsigned int r = *(const unsigned int*)(hw + (size_t)s * HCn + lane * FPL);
        float w = __expf(lrelu(alo[s] + ahin));
        den += w;
        float2 f = __bfloat1622float2(*(__nv_bfloat162*)&r);
        a0 += w * f.x; a1 += w * f.y;
    }
    float inv_d = 1.f / (den + 1e-16f);
    float v0 = a0 * inv_d + bias[lane * FPL];
    float v1 = a1 * inv_d + bias[lane * FPL + 1];
    v0 = (v0 > 0.f) ? v0 : expm1f(v0);
    v1 = (v1 > 0.f) ? v1 : expm1f(v1);

    int b = batch[n];
    atomicAdd(&g_pool[b * HIDDEN + lane * FPL], v0);
    atomicAdd(&g_pool[b * HIDDEN + lane * FPL + 1], v1);
    if (lane == 0) atomicAdd(&g_cnt[b], 1.f);
}

// ---------------------------------------------------------------------------
// Heads MLP
// ---------------------------------------------------------------------------
__global__ void k_mlp(const float* __restrict__ Wc1, const float* __restrict__ bc1,
                      const float* __restrict__ Wc2, const float* __restrict__ bc2,
                      const float* __restrict__ Wr1, const float* __restrict__ br1,
                      const float* __restrict__ Wr2, const float* __restrict__ br2,
                      float* __restrict__ out) {
    int warp = (blockIdx.x * blockDim.x + threadIdx.x) >> 5;
    int lane = threadIdx.x & 31;
    if (warp >= NGRAPHS) return;
    float inv_cnt = 1.f / fmaxf(g_cnt[warp], 1.f);
    const float* gp = &g_pool[warp * HIDDEN];

    {
        float h0 = bc1[lane], h1 = bc1[lane + 32];
        for (int c = 0; c < HIDDEN; c++) {
            float gc = gp[c] * inv_cnt;
            h0 += Wc1[lane * HIDDEN + c] * gc;
            h1 += Wc1[(lane + 32) * HIDDEN + c] * gc;
        }
        h0 = fmaxf(h0, 0.f); h1 = fmaxf(h1, 0.f);
        float s = Wc2[lane] * h0 + Wc2[lane + 32] * h1;
        #pragma unroll
        for (int off = 16; off > 0; off >>= 1) s += __shfl_xor_sync(0xffffffffu, s, off);
        if (lane == 0) out[warp] = s + bc2[0];
    }
    {
        float h0 = br1[lane], h1 = br1[lane + 32];
        for (int c = 0; c < HIDDEN; c++) {
            float gc = gp[c] * inv_cnt;
            h0 += Wr1[lane * HIDDEN + c] * gc;
            h1 += Wr1[(lane + 32) * HIDDEN + c] * gc;
        }
        h0 = fmaxf(h0, 0.f); h1 = fmaxf(h1, 0.f);
        float s = Wr2[lane] * h0 + Wr2[lane + 32] * h1;
        #pragma unroll
        for (int off = 16; off > 0; off >>= 1) s += __shfl_xor_sync(0xffffffffu, s, off);
        if (lane == 0) out[NGRAPHS + warp] = s + br2[0];
    }
}

// ---------------------------------------------------------------------------
// Launch
// ---------------------------------------------------------------------------
extern "C" void kernel_launch(void* const* d_in, const int* in_sizes, int n_in,
                              void* d_out, int out_size) {
    const float* x     = (const float*)d_in[0];
    const int*   ei    = (const int*)d_in[1];
    const int*   batch = (const int*)d_in[2];
    const float* W1  = (const float*)d_in[3];
    const float* as1 = (const float*)d_in[4];
    const float* ad1 = (const float*)d_in[5];
    const float* b1  = (const float*)d_in[6];
    const float* W2  = (const float*)d_in[7];
    const float* as2 = (const float*)d_in[8];
    const float* ad2 = (const float*)d_in[9];
    const float* b2  = (const float*)d_in[10];
    const float* W3  = (const float*)d_in[11];
    const float* as3 = (const float*)d_in[12];
    const float* ad3 = (const float*)d_in[13];
    const float* b3  = (const float*)d_in[14];
    const float* Wc1 = (const float*)d_in[15];
    const float* bc1 = (const float*)d_in[16];
    const float* Wc2 = (const float*)d_in[17];
    const float* bc2 = (const float*)d_in[18];
    const float* Wr1 = (const float*)d_in[19];
    const float* br1 = (const float*)d_in[20];
    const float* Wr2 = (const float*)d_in[21];
    const float* br2 = (const float*)d_in[22];
    float* out = (float*)d_out;

    const int* srcp = ei;
    const int* dstp = ei + NEDGES;

    __nv_bfloat16 *hw_p, *xbf_p, *featb_p, *w1h_p, *w1l_p, *w2h_p, *w2l_p, *w3h_p, *w3l_p;
    cudaGetSymbolAddress((void**)&hw_p,    g_hw);
    cudaGetSymbolAddress((void**)&xbf_p,   g_xbf);
    cudaGetSymbolAddress((void**)&featb_p, g_featb);
    cudaGetSymbolAddress((void**)&w1h_p,   g_W1h);
    cudaGetSymbolAddress((void**)&w1l_p,   g_W1l);
    cudaGetSymbolAddress((void**)&w2h_p,   g_W2h);
    cudaGetSymbolAddress((void**)&w2l_p,   g_W2l);
    cudaGetSymbolAddress((void**)&w3h_p,   g_W3h);
    cudaGetSymbolAddress((void**)&w3l_p,   g_W3l);
    float *alo_p, *ahi_p;
    cudaGetSymbolAddress((void**)&alo_p, g_alo);
    cudaGetSymbolAddress((void**)&ahi_p, g_ahi);

    const int warps_grid = (NNODES * 32 + 255) / 256;
    const int mblocks = (NNODES + GBM - 1) / GBM;

    k_zero_csr<<<(NNODES + 256) / 256, 256>>>();
    k_pre<<<(NNODES * IN_DIM / 2 + 255) / 256, 256>>>(x, W1, W2, W3, dstp);
    k_scan<<<1, 1024>>>();
    k_gemm_w<<<dim3(HC1 / 128, mblocks), 256>>>(xbf_p, w1h_p, w1l_p, hw_p, NNODES, HC1, IN_DIM,
                                                as1, ad1, alo_p, ahi_p, HEADS);
    k_scatter<<<(NEDGES + 255) / 256, 256>>>(srcp, dstp);

    k_aggregate4<<<warps_grid, 256>>>(hw_p, alo_p, ahi_p, b1, featb_p);
    k_gemm_w<<<dim3(HC1 / 128, mblocks), 256>>>(featb_p, w2h_p, w2l_p, hw_p, NNODES, HC1, HC1,
                                                as2, ad2, alo_p, ahi_p, HEADS);
    k_aggregate4<<<warps_grid, 256>>>(hw_p, alo_p, ahi_p, b2, featb_p);
    k_gemm_bb<<<dim3(1, mblocks), 256>>>(featb_p, w3h_p, w3l_p, hw_p, NNODES, HIDDEN, HC1,
                                         as3, ad3, alo_p, ahi_p, 1);
    k_aggregate1_pool<<<warps_grid, 256>>>(hw_p, alo_p, ahi_p, b3, batch);

    k_mlp<<<(NGRAPHS * 32 + 255) / 256, 256>>>(Wc1, bc1, Wc2, bc2, Wr1, br1, Wr2, br2, out);
}